// round 12
// baseline (speedup 1.0000x reference)
#include <cuda_runtime.h>
#include <cuda_bf16.h>
#include <math.h>
#include <stdint.h>

// Shapes
#define NB   64
#define T1   33
#define TL   32
#define I1   197
#define IP   224      // padded i
#define CD   512
#define TEMP 0.07f
#define QS   127.0f
#define OSCALE (TEMP / (QS * QS))
#define NCH  4        // K chunks of 128 (int8: 128B rows)
#define A_CH 8192     // A chunk image: 64 rows x 128B
#define B_CH 28672    // B chunk image: 224 rows x 128B
#define NCTA 2048     // 32 x 64

// Scratch: pre-swizzled, chunk-major int8 SMEM images
__device__ __align__(256) int8_t g_Asw[32 * NCH * A_CH];
__device__ __align__(256) int8_t g_Bsw[NB * NCH * B_CH];
__device__ float g_tti[NB * NB];
__device__ int   g_cnt;

// ---------------------------------------------------------------------------
__device__ __forceinline__ uint32_t smem_u32(const void* p) {
    uint32_t a;
    asm("{ .reg .u64 t; cvta.to.shared.u64 t, %1; cvt.u32.u64 %0, t; }"
        : "=r"(a) : "l"(p));
    return a;
}
#define SWZ(o) ((o) ^ ((((uint32_t)(o)) >> 3) & 0x70u))

__device__ __forceinline__ void bulk_ld(uint32_t dst, const void* src,
                                        uint32_t bytes, uint32_t mbar) {
    asm volatile(
        "cp.async.bulk.shared::cluster.global.mbarrier::complete_tx::bytes "
        "[%0], [%1], %2, [%3];"
        :: "r"(dst), "l"(src), "r"(bytes), "r"(mbar) : "memory");
}
__device__ __forceinline__ void mbar_init(uint32_t m, uint32_t cnt) {
    asm volatile("mbarrier.init.shared.b64 [%0], %1;" :: "r"(m), "r"(cnt) : "memory");
}
__device__ __forceinline__ void mbar_expect(uint32_t m, uint32_t bytes) {
    asm volatile("mbarrier.arrive.expect_tx.shared.b64 _, [%0], %1;"
                 :: "r"(m), "r"(bytes) : "memory");
}
__device__ __forceinline__ void mbar_arrive(uint32_t m) {
    asm volatile("mbarrier.arrive.shared.b64 _, [%0];" :: "r"(m) : "memory");
}
#define MBAR_WAIT(addr, par) do {                                               \
    uint32_t _m = (addr), _p = (par), _d;                                       \
    asm volatile("{\n\t.reg .pred p;\n\t"                                       \
        "mbarrier.try_wait.parity.acquire.cta.shared::cta.b64 p, [%1], %2;\n\t" \
        "selp.b32 %0, 1, 0, p;\n\t}" : "=r"(_d) : "r"(_m), "r"(_p) : "memory"); \
    if (!_d) {                                                                  \
        asm volatile("{\n\t.reg .pred P1;\n\tWL_%=:\n\t"                        \
            "mbarrier.try_wait.parity.acquire.cta.shared::cta.b64 P1, [%0], %1, 0x989680;\n\t" \
            "@P1 bra.uni WD_%=;\n\tbra.uni WL_%=;\n\tWD_%=:\n\t}"               \
            :: "r"(_m), "r"(_p) : "memory");                                    \
    }                                                                           \
} while (0)

__device__ __forceinline__ void ldm_x4(uint32_t* r, uint32_t a) {
    asm volatile("ldmatrix.sync.aligned.m8n8.x4.shared.b16 {%0,%1,%2,%3}, [%4];"
                 : "=r"(r[0]), "=r"(r[1]), "=r"(r[2]), "=r"(r[3]) : "r"(a));
}
__device__ __forceinline__ void ldm_x2(uint32_t* r, uint32_t a) {
    asm volatile("ldmatrix.sync.aligned.m8n8.x2.shared.b16 {%0,%1}, [%2];"
                 : "=r"(r[0]), "=r"(r[1]) : "r"(a));
}
__device__ __forceinline__ void mma_s8(int* d, const uint32_t* a,
                                       uint32_t b0, uint32_t b1) {
    asm volatile(
        "mma.sync.aligned.m16n8k32.row.col.s32.s8.s8.s32 "
        "{%0,%1,%2,%3}, {%4,%5,%6,%7}, {%8,%9}, {%0,%1,%2,%3};"
        : "+r"(d[0]), "+r"(d[1]), "+r"(d[2]), "+r"(d[3])
        : "r"(a[0]), "r"(a[1]), "r"(a[2]), "r"(a[3]), "r"(b0), "r"(b1));
}

__device__ __forceinline__ int8_t to_s8(float v) {
    return (int8_t)__float2int_rn(v * QS);
}

// ---------------------------------------------------------------------------
// knorm: grid (64,2), block 256. Thread handles 2 d-columns via float2.
// by==0 -> text, by==1 -> video (unroll-8 for MLP). int8 swizzled output.
// ---------------------------------------------------------------------------
__global__ void knorm(const float* __restrict__ text, const float* __restrict__ video) {
    const int b = blockIdx.x, tid = threadIdx.x;
    const int d = 2 * tid;                       // first of 2 columns
    if (blockIdx.y == 0) {
        if (b == 0 && tid == 0) g_cnt = 0;
        const float2* p2 = (const float2*)(text + (size_t)b * T1 * CD) + tid;
        float s0 = 0.f, s1 = 0.f;
#pragma unroll
        for (int t = 0; t < T1; t++) {
            float2 v = p2[t * (CD / 2)];
            s0 += v.x * v.x; s1 += v.y * v.y;
        }
        float i0 = 1.0f / sqrtf(s0), i1 = 1.0f / sqrtf(s1);
        int8_t* base = g_Asw + (((size_t)(b >> 1)) * NCH + (d >> 7)) * A_CH;
        uint32_t colb = d & 127;
#pragma unroll 4
        for (int t = 0; t < TL; t++) {
            float2 v = p2[(t + 1) * (CD / 2)];
            int row = (b & 1) * 32 + t;
            uchar2 o = { (unsigned char)to_s8(v.x * i0), (unsigned char)to_s8(v.y * i1) };
            *(uchar2*)(base + SWZ(row * 128 + colb)) = o;
        }
    } else {
        const float2* p2 = (const float2*)(video + (size_t)b * I1 * CD) + tid;
        float s0 = 0.f, s1 = 0.f;
#pragma unroll 8
        for (int t = 0; t < I1; t++) {
            float2 v = p2[t * (CD / 2)];
            s0 += v.x * v.x; s1 += v.y * v.y;
        }
        float i0 = 1.0f / sqrtf(s0), i1 = 1.0f / sqrtf(s1);
        int8_t* base = g_Bsw + ((size_t)b * NCH + (d >> 7)) * B_CH;
        uint32_t colb = d & 127;
#pragma unroll 4
        for (int t = 0; t < I1; t++) {
            float2 v = p2[t * (CD / 2)];
            uchar2 o = { (unsigned char)to_s8(v.x * i0), (unsigned char)to_s8(v.y * i1) };
            *(uchar2*)(base + SWZ(t * 128 + colb)) = o;
        }
        uchar2 z = { 0, 0 };
        for (int t = I1; t < IP; t++)
            *(uchar2*)(base + SWZ(t * 128 + colb)) = z;
    }
}

// ---------------------------------------------------------------------------
// ksim: CTA (qh,y): D[64,224] = A(64x512)*B(224x512)^T in s8->s32.
// 8 warps 2(M)x4(N), warp tile 32x56, K-chunks of 128 (4 x k32 steps),
// 2-stage bulk ring, OCCUPANCY 3 (register diet: single-buffered frags,
// 6 precomputed swizzled addrs, ks offset folded as XOR immediate).
// ---------------------------------------------------------------------------
#define SM_RMAX  0
#define SM_MBF   1024        // full barriers (2 x 8B)
#define SM_MBE   1040        // empty barriers (2 x 8B)
#define SM_STG   2048
#define STG_SZ   (A_CH + B_CH)              // 36864
#define SM_TOTAL (SM_STG + 2 * STG_SZ)      // 75776

__global__ void __launch_bounds__(256, 3)
ksim(const int* __restrict__ amask, float* __restrict__ out) {
    extern __shared__ char smem[];
    __shared__ int lastflag;
    const uint32_t sb = smem_u32(smem);
    const int tid = threadIdx.x, wid = tid >> 5, lid = tid & 31;
    const int wm = wid & 1, wn = wid >> 1;
    const int qh = blockIdx.x, y = blockIdx.y;

    const int8_t* Asrc = g_Asw + (size_t)qh * NCH * A_CH;
    const int8_t* Bsrc = g_Bsw + (size_t)y * NCH * B_CH;

    if (tid == 0) {
#pragma unroll
        for (int s = 0; s < 2; s++) {
            mbar_init(sb + SM_MBF + 8 * s, 1);
            mbar_init(sb + SM_MBE + 8 * s, 8);
        }
    }
    __syncthreads();
    if (tid == 0) {
#pragma unroll
        for (int s = 0; s < 2; s++) {                 // prologue: chunks 0..1
            uint32_t mb = sb + SM_MBF + 8 * s;
            uint32_t st = sb + SM_STG + s * STG_SZ;
            mbar_expect(mb, STG_SZ);
            bulk_ld(st,        Asrc + (size_t)s * A_CH, A_CH, mb);
            bulk_ld(st + A_CH, Bsrc + (size_t)s * B_CH, B_CH, mb);
        }
    }

    int acc[2][7][4];
#pragma unroll
    for (int mi = 0; mi < 2; mi++)
#pragma unroll
        for (int nj = 0; nj < 7; nj++)
#pragma unroll
            for (int d = 0; d < 4; d++) acc[mi][nj][d] = 0;

    // 6 precomputed swizzled fragment offsets (ks offset = XOR of kb: bits 5-6
    // of the base are zero, so SWZ(x + kb) == SWZ(x) ^ kb).
    const int arow = 32 * wm + (lid & 15);
    const int brow = 56 * wn + (lid & 15);
    const int btr  = 56 * wn + 48 + (lid & 7);
    const uint32_t chi = ((uint32_t)lid >> 4) * 16;
    const uint32_t cht = (((uint32_t)lid >> 3) & 1) * 16;
    const uint32_t swA0 = SWZ((uint32_t)(arow)      * 128 + chi);
    const uint32_t swA1 = SWZ((uint32_t)(arow + 16) * 128 + chi);
    const uint32_t swB0 = SWZ((uint32_t)(brow)      * 128 + chi);
    const uint32_t swB1 = SWZ((uint32_t)(brow + 16) * 128 + chi);
    const uint32_t swB2 = SWZ((uint32_t)(brow + 32) * 128 + chi);
    const uint32_t swBT = SWZ((uint32_t)(btr)       * 128 + cht);

#pragma unroll 1
    for (int c = 0; c < NCH; c++) {
        const int s = c & 1;
        MBAR_WAIT(sb + SM_MBF + 8 * s, (c >> 1) & 1);
        const uint32_t stA = sb + SM_STG + s * STG_SZ;
        const uint32_t stB = stA + A_CH;

#pragma unroll
        for (int ks = 0; ks < 4; ks++) {
            const uint32_t kb = (uint32_t)ks * 32;    // XOR-foldable immediate
            uint32_t af[2][4], bf[3][4], bt[2];
            ldm_x4(af[0], stA + (swA0 ^ kb));
            ldm_x4(af[1], stA + (swA1 ^ kb));
            ldm_x4(bf[0], stB + (swB0 ^ kb));
            ldm_x4(bf[1], stB + (swB1 ^ kb));
            ldm_x4(bf[2], stB + (swB2 ^ kb));
            ldm_x2(bt,    stB + (swBT ^ kb));
#pragma unroll
            for (int mi = 0; mi < 2; mi++) {
#pragma unroll
                for (int ni = 0; ni < 3; ni++) {
                    mma_s8(acc[mi][2 * ni],     af[mi], bf[ni][0], bf[ni][2]);
                    mma_s8(acc[mi][2 * ni + 1], af[mi], bf[ni][1], bf[ni][3]);
                }
                mma_s8(acc[mi][6], af[mi], bt[0], bt[1]);
            }
        }
        if (lid == 0) mbar_arrive(sb + SM_MBE + 8 * s);

        if (tid == 0 && c < NCH - 2) {                // refill stage s, chunk c+2
            MBAR_WAIT(sb + SM_MBE + 8 * s, 0);
            uint32_t mb = sb + SM_MBF + 8 * s;
            mbar_expect(mb, STG_SZ);
            bulk_ld(stA, Asrc + (size_t)(c + 2) * A_CH, A_CH, mb);
            bulk_ld(stB, Bsrc + (size_t)(c + 2) * B_CH, B_CH, mb);
        }
    }

    // ---- Epilogue: per-row int max over i (mask i>=197) -> masked mean over t
    float* rowmax = (float*)(smem + SM_RMAX);          // [64][4]
#pragma unroll
    for (int mi = 0; mi < 2; mi++)
#pragma unroll
        for (int h = 0; h < 2; h++) {
            int m = -2147483647;
#pragma unroll
            for (int nj = 0; nj < 7; nj++)
#pragma unroll
                for (int e = 0; e < 2; e++) {
                    int col = 56 * wn + 8 * nj + 2 * (lid & 3) + e;
                    int v = acc[mi][nj][2 * h + e];
                    if (col < I1) m = max(m, v);
                }
            m = max(m, __shfl_xor_sync(0xffffffffu, m, 1));
            m = max(m, __shfl_xor_sync(0xffffffffu, m, 2));
            if ((lid & 3) == 0) {
                int row = 32 * wm + 16 * mi + 8 * h + (lid >> 2);
                rowmax[4 * row + wn] = (float)m;
            }
        }
    __syncthreads();

    if (tid < 64) {
        int row = tid;
        float m = fmaxf(fmaxf(rowmax[4 * row], rowmax[4 * row + 1]),
                        fmaxf(rowmax[4 * row + 2], rowmax[4 * row + 3]));
        int xl = row >> 5, t = row & 31;
        int x = 2 * qh + xl;
        int mk = amask[x * T1 + 1 + t] != 0;
        float v = mk ? m * OSCALE : 0.f;
        float cnt = mk ? 1.f : 0.f;
#pragma unroll
        for (int o = 16; o > 0; o >>= 1) {
            v   += __shfl_xor_sync(0xffffffffu, v, o);
            cnt += __shfl_xor_sync(0xffffffffu, cnt, o);
        }
        if (t == 0) g_tti[x * NB + y] = v / fmaxf(cnt, 1e-6f);
    }
    __syncthreads();

    // ---- Last CTA computes the loss
    if (tid == 0) {
        __threadfence();
        lastflag = (atomicAdd(&g_cnt, 1) == NCTA - 1);
    }
    __syncthreads();
    if (lastflag) {
        __threadfence();
        float* sl = (float*)(smem + SM_RMAX);
#pragma unroll 1
        for (int rep = 0; rep < 8; rep++) {
            int x = 8 * wid + rep;
            const float* row = g_tti + x * NB;
            float e = expf(row[lid]) + expf(row[lid + 32]);
#pragma unroll
            for (int o = 16; o > 0; o >>= 1) e += __shfl_xor_sync(0xffffffffu, e, o);
            if (lid == 0) sl[x] = -logf(expf(row[x]) / e + 1e-20f);
        }
        __syncthreads();
        if (tid < 32) {
            float s = sl[lid] + sl[lid + 32];
#pragma unroll
            for (int o = 16; o > 0; o >>= 1) s += __shfl_xor_sync(0xffffffffu, s, o);
            if (lid == 0) out[0] = s * (1.0f / NB);
        }
    }
}

// ---------------------------------------------------------------------------
extern "C" void kernel_launch(void* const* d_in, const int* in_sizes, int n_in,
                              void* d_out, int out_size) {
    const float* text  = (const float*)d_in[0];
    const float* video = (const float*)d_in[1];
    const int*   mask  = (const int*)d_in[2];

    static int smem_set = 0;
    if (!smem_set) {
        cudaFuncSetAttribute(ksim, cudaFuncAttributeMaxDynamicSharedMemorySize, SM_TOTAL);
        smem_set = 1;
    }

    knorm<<<dim3(NB, 2), 256>>>(text, video);
    ksim<<<dim3(32, NB), 256, SM_TOTAL>>>(mask, (float*)d_out);
}

// round 13
// speedup vs baseline: 1.3183x; 1.3183x over previous
#include <cuda_runtime.h>
#include <cuda_bf16.h>
#include <math.h>
#include <stdint.h>

// Shapes
#define NB   64
#define T1   33
#define TL   32
#define I1   197
#define IP   224      // padded i
#define CD   512
#define TEMP 0.07f
#define QS   127.0f
#define OSCALE (TEMP / (QS * QS))
#define NCH  4        // K chunks of 128 (int8: 128B rows)
#define A_CH 8192     // A chunk image: 64 rows x 128B
#define B_CH 28672    // B chunk image: 224 rows x 128B
#define NCTA 2048     // 32 x 64

// Scratch: pre-swizzled, chunk-major int8 SMEM images
__device__ __align__(256) int8_t g_Asw[32 * NCH * A_CH];
__device__ __align__(256) int8_t g_Bsw[NB * NCH * B_CH];
__device__ float g_tti[NB * NB];
__device__ int   g_cnt;

// ---------------------------------------------------------------------------
__device__ __forceinline__ uint32_t smem_u32(const void* p) {
    uint32_t a;
    asm("{ .reg .u64 t; cvta.to.shared.u64 t, %1; cvt.u32.u64 %0, t; }"
        : "=r"(a) : "l"(p));
    return a;
}
#define SWZ(o) ((o) ^ ((((uint32_t)(o)) >> 3) & 0x70u))

__device__ __forceinline__ void bulk_ld(uint32_t dst, const void* src,
                                        uint32_t bytes, uint32_t mbar) {
    asm volatile(
        "cp.async.bulk.shared::cluster.global.mbarrier::complete_tx::bytes "
        "[%0], [%1], %2, [%3];"
        :: "r"(dst), "l"(src), "r"(bytes), "r"(mbar) : "memory");
}
__device__ __forceinline__ void mbar_init(uint32_t m, uint32_t cnt) {
    asm volatile("mbarrier.init.shared.b64 [%0], %1;" :: "r"(m), "r"(cnt) : "memory");
}
__device__ __forceinline__ void mbar_expect(uint32_t m, uint32_t bytes) {
    asm volatile("mbarrier.arrive.expect_tx.shared.b64 _, [%0], %1;"
                 :: "r"(m), "r"(bytes) : "memory");
}
__device__ __forceinline__ void mbar_arrive(uint32_t m) {
    asm volatile("mbarrier.arrive.shared.b64 _, [%0];" :: "r"(m) : "memory");
}
#define MBAR_WAIT(addr, par) do {                                               \
    uint32_t _m = (addr), _p = (par), _d;                                       \
    asm volatile("{\n\t.reg .pred p;\n\t"                                       \
        "mbarrier.try_wait.parity.acquire.cta.shared::cta.b64 p, [%1], %2;\n\t" \
        "selp.b32 %0, 1, 0, p;\n\t}" : "=r"(_d) : "r"(_m), "r"(_p) : "memory"); \
    if (!_d) {                                                                  \
        asm volatile("{\n\t.reg .pred P1;\n\tWL_%=:\n\t"                        \
            "mbarrier.try_wait.parity.acquire.cta.shared::cta.b64 P1, [%0], %1, 0x989680;\n\t" \
            "@P1 bra.uni WD_%=;\n\tbra.uni WL_%=;\n\tWD_%=:\n\t}"               \
            :: "r"(_m), "r"(_p) : "memory");                                    \
    }                                                                           \
} while (0)

__device__ __forceinline__ void ldm_x4(uint32_t* r, uint32_t a) {
    asm volatile("ldmatrix.sync.aligned.m8n8.x4.shared.b16 {%0,%1,%2,%3}, [%4];"
                 : "=r"(r[0]), "=r"(r[1]), "=r"(r[2]), "=r"(r[3]) : "r"(a));
}
__device__ __forceinline__ void ldm_x2(uint32_t* r, uint32_t a) {
    asm volatile("ldmatrix.sync.aligned.m8n8.x2.shared.b16 {%0,%1}, [%2];"
                 : "=r"(r[0]), "=r"(r[1]) : "r"(a));
}
__device__ __forceinline__ void mma_s8(int* d, const uint32_t* a,
                                       uint32_t b0, uint32_t b1) {
    asm volatile(
        "mma.sync.aligned.m16n8k32.row.col.s32.s8.s8.s32 "
        "{%0,%1,%2,%3}, {%4,%5,%6,%7}, {%8,%9}, {%0,%1,%2,%3};"
        : "+r"(d[0]), "+r"(d[1]), "+r"(d[2]), "+r"(d[3])
        : "r"(a[0]), "r"(a[1]), "r"(a[2]), "r"(a[3]), "r"(b0), "r"(b1));
}

__device__ __forceinline__ int8_t to_s8(float v) {
    return (int8_t)__float2int_rn(v * QS);
}

// ---------------------------------------------------------------------------
// knorm: grid (64,2), block 256. Thread handles 2 d-columns via float2.
// by==0 -> text, by==1 -> video (unroll-16 for MLP). int8 swizzled output.
// ---------------------------------------------------------------------------
__global__ void knorm(const float* __restrict__ text, const float* __restrict__ video) {
    const int b = blockIdx.x, tid = threadIdx.x;
    const int d = 2 * tid;
    if (blockIdx.y == 0) {
        if (b == 0 && tid == 0) g_cnt = 0;
        const float2* p2 = (const float2*)(text + (size_t)b * T1 * CD) + tid;
        float s0 = 0.f, s1 = 0.f;
#pragma unroll
        for (int t = 0; t < T1; t++) {
            float2 v = p2[t * (CD / 2)];
            s0 += v.x * v.x; s1 += v.y * v.y;
        }
        float i0 = 1.0f / sqrtf(s0), i1 = 1.0f / sqrtf(s1);
        int8_t* base = g_Asw + (((size_t)(b >> 1)) * NCH + (d >> 7)) * A_CH;
        uint32_t colb = d & 127;
#pragma unroll 4
        for (int t = 0; t < TL; t++) {
            float2 v = p2[(t + 1) * (CD / 2)];
            int row = (b & 1) * 32 + t;
            uchar2 o = { (unsigned char)to_s8(v.x * i0), (unsigned char)to_s8(v.y * i1) };
            *(uchar2*)(base + SWZ(row * 128 + colb)) = o;
        }
    } else {
        const float2* p2 = (const float2*)(video + (size_t)b * I1 * CD) + tid;
        float s0 = 0.f, s1 = 0.f;
#pragma unroll 16
        for (int t = 0; t < I1; t++) {
            float2 v = p2[t * (CD / 2)];
            s0 += v.x * v.x; s1 += v.y * v.y;
        }
        float i0 = 1.0f / sqrtf(s0), i1 = 1.0f / sqrtf(s1);
        int8_t* base = g_Bsw + ((size_t)b * NCH + (d >> 7)) * B_CH;
        uint32_t colb = d & 127;
#pragma unroll 4
        for (int t = 0; t < I1; t++) {
            float2 v = p2[t * (CD / 2)];
            uchar2 o = { (unsigned char)to_s8(v.x * i0), (unsigned char)to_s8(v.y * i1) };
            *(uchar2*)(base + SWZ(t * 128 + colb)) = o;
        }
        uchar2 z = { 0, 0 };
        for (int t = I1; t < IP; t++)
            *(uchar2*)(base + SWZ(t * 128 + colb)) = z;
    }
}

// ---------------------------------------------------------------------------
// ksim: CTA (qh,y): D[64,224] = A(64x512)*B(224x512)^T in s8->s32.
// 8 warps 2(M)x4(N), warp tile 32x56, K-chunks of 128 (4 x k32 steps),
// 3-stage bulk ring, occupancy 2. ANTI-CONVOY: warp w rotates its k32-step
// order ((ks+wid)&3) so LDSM and IMMA phases of co-resident warps overlap.
// ---------------------------------------------------------------------------
#define SM_RMAX  0
#define SM_MBF   1024
#define SM_MBE   1088
#define SM_STG   2048
#define STG_SZ   (A_CH + B_CH)              // 36864
#define SM_TOTAL (SM_STG + 3 * STG_SZ)      // 112640

__global__ void __launch_bounds__(256, 2)
ksim(const int* __restrict__ amask, float* __restrict__ out) {
    extern __shared__ char smem[];
    __shared__ int lastflag;
    const uint32_t sb = smem_u32(smem);
    const int tid = threadIdx.x, wid = tid >> 5, lid = tid & 31;
    const int wm = wid & 1, wn = wid >> 1;
    const int qh = blockIdx.x, y = blockIdx.y;

    const int8_t* Asrc = g_Asw + (size_t)qh * NCH * A_CH;
    const int8_t* Bsrc = g_Bsw + (size_t)y * NCH * B_CH;

    if (tid == 0) {
#pragma unroll
        for (int s = 0; s < 3; s++) {
            mbar_init(sb + SM_MBF + 8 * s, 1);
            mbar_init(sb + SM_MBE + 8 * s, 8);
        }
    }
    __syncthreads();
    if (tid == 0) {
#pragma unroll
        for (int s = 0; s < 3; s++) {                 // prologue: chunks 0..2
            uint32_t mb = sb + SM_MBF + 8 * s;
            uint32_t st = sb + SM_STG + s * STG_SZ;
            mbar_expect(mb, STG_SZ);
            bulk_ld(st,        Asrc + (size_t)s * A_CH, A_CH, mb);
            bulk_ld(st + A_CH, Bsrc + (size_t)s * B_CH, B_CH, mb);
        }
    }

    int acc[2][7][4];
#pragma unroll
    for (int mi = 0; mi < 2; mi++)
#pragma unroll
        for (int nj = 0; nj < 7; nj++)
#pragma unroll
            for (int d = 0; d < 4; d++) acc[mi][nj][d] = 0;

    // Precomputed swizzled fragment offsets; per-ks offset is an XOR of kb
    // (bits 5-6 of the base byte offsets are zero within a 32B-aligned k-seg).
    const int arow = 32 * wm + (lid & 15);
    const int brow = 56 * wn + (lid & 15);
    const int btr  = 56 * wn + 48 + (lid & 7);
    const uint32_t chi = ((uint32_t)lid >> 4) * 16;
    const uint32_t cht = (((uint32_t)lid >> 3) & 1) * 16;
    const uint32_t swA0 = SWZ((uint32_t)(arow)      * 128 + chi);
    const uint32_t swA1 = SWZ((uint32_t)(arow + 16) * 128 + chi);
    const uint32_t swB0 = SWZ((uint32_t)(brow)      * 128 + chi);
    const uint32_t swB1 = SWZ((uint32_t)(brow + 16) * 128 + chi);
    const uint32_t swB2 = SWZ((uint32_t)(brow + 32) * 128 + chi);
    const uint32_t swBT = SWZ((uint32_t)(btr)       * 128 + cht);

    int cs = 0;
    uint32_t ph = 0, eph = 0;

#pragma unroll 1
    for (int c = 0; c < NCH; c++) {
        const int s = cs;
        cs = (cs == 2) ? 0 : cs + 1;
        MBAR_WAIT(sb + SM_MBF + 8 * s, (ph >> s) & 1);
        ph ^= (1u << s);
        const uint32_t stA = sb + SM_STG + s * STG_SZ;
        const uint32_t stB = stA + A_CH;

#pragma unroll
        for (int ks = 0; ks < 4; ks++) {
            // Anti-convoy rotation: warp wid starts at k-step (wid&3).
            const uint32_t kb = (uint32_t)(((ks + wid) & 3) * 32);
            uint32_t af[2][4], bf[3][4], bt[2];
            ldm_x4(af[0], stA + (swA0 ^ kb));
            ldm_x4(af[1], stA + (swA1 ^ kb));
            ldm_x4(bf[0], stB + (swB0 ^ kb));
            ldm_x4(bf[1], stB + (swB1 ^ kb));
            ldm_x4(bf[2], stB + (swB2 ^ kb));
            ldm_x2(bt,    stB + (swBT ^ kb));
#pragma unroll
            for (int mi = 0; mi < 2; mi++) {
#pragma unroll
                for (int ni = 0; ni < 3; ni++) {
                    mma_s8(acc[mi][2 * ni],     af[mi], bf[ni][0], bf[ni][2]);
                    mma_s8(acc[mi][2 * ni + 1], af[mi], bf[ni][1], bf[ni][3]);
                }
                mma_s8(acc[mi][6], af[mi], bt[0], bt[1]);
            }
        }
        if (lid == 0) mbar_arrive(sb + SM_MBE + 8 * s);

        if (tid == 0 && c < NCH - 3) {                // refill stage s, chunk c+3
            MBAR_WAIT(sb + SM_MBE + 8 * s, (eph >> s) & 1);
            eph ^= (1u << s);
            uint32_t mb = sb + SM_MBF + 8 * s;
            mbar_expect(mb, STG_SZ);
            bulk_ld(stA, Asrc + (size_t)(c + 3) * A_CH, A_CH, mb);
            bulk_ld(stB, Bsrc + (size_t)(c + 3) * B_CH, B_CH, mb);
        }
    }

    // ---- Epilogue: per-row int max over i (mask i>=197) -> masked mean over t
    float* rowmax = (float*)(smem + SM_RMAX);          // [64][4]
#pragma unroll
    for (int mi = 0; mi < 2; mi++)
#pragma unroll
        for (int h = 0; h < 2; h++) {
            int m = -2147483647;
#pragma unroll
            for (int nj = 0; nj < 7; nj++)
#pragma unroll
                for (int e = 0; e < 2; e++) {
                    int col = 56 * wn + 8 * nj + 2 * (lid & 3) + e;
                    int v = acc[mi][nj][2 * h + e];
                    if (col < I1) m = max(m, v);
                }
            m = max(m, __shfl_xor_sync(0xffffffffu, m, 1));
            m = max(m, __shfl_xor_sync(0xffffffffu, m, 2));
            if ((lid & 3) == 0) {
                int row = 32 * wm + 16 * mi + 8 * h + (lid >> 2);
                rowmax[4 * row + wn] = (float)m;
            }
        }
    __syncthreads();

    if (tid < 64) {
        int row = tid;
        float m = fmaxf(fmaxf(rowmax[4 * row], rowmax[4 * row + 1]),
                        fmaxf(rowmax[4 * row + 2], rowmax[4 * row + 3]));
        int xl = row >> 5, t = row & 31;
        int x = 2 * qh + xl;
        int mk = amask[x * T1 + 1 + t] != 0;
        float v = mk ? m * OSCALE : 0.f;
        float cnt = mk ? 1.f : 0.f;
#pragma unroll
        for (int o = 16; o > 0; o >>= 1) {
            v   += __shfl_xor_sync(0xffffffffu, v, o);
            cnt += __shfl_xor_sync(0xffffffffu, cnt, o);
        }
        if (t == 0) g_tti[x * NB + y] = v / fmaxf(cnt, 1e-6f);
    }
    __syncthreads();

    // ---- Last CTA computes the loss
    if (tid == 0) {
        __threadfence();
        lastflag = (atomicAdd(&g_cnt, 1) == NCTA - 1);
    }
    __syncthreads();
    if (lastflag) {
        __threadfence();
        float* sl = (float*)(smem + SM_RMAX);
#pragma unroll 1
        for (int rep = 0; rep < 8; rep++) {
            int x = 8 * wid + rep;
            const float* row = g_tti + x * NB;
            float e = expf(row[lid]) + expf(row[lid + 32]);
#pragma unroll
            for (int o = 16; o > 0; o >>= 1) e += __shfl_xor_sync(0xffffffffu, e, o);
            if (lid == 0) sl[x] = -logf(expf(row[x]) / e + 1e-20f);
        }
        __syncthreads();
        if (tid < 32) {
            float s = sl[lid] + sl[lid + 32];
#pragma unroll
            for (int o = 16; o > 0; o >>= 1) s += __shfl_xor_sync(0xffffffffu, s, o);
            if (lid == 0) out[0] = s * (1.0f / NB);
        }
    }
}

// ---------------------------------------------------------------------------
extern "C" void kernel_launch(void* const* d_in, const int* in_sizes, int n_in,
                              void* d_out, int out_size) {
    const float* text  = (const float*)d_in[0];
    const float* video = (const float*)d_in[1];
    const int*   mask  = (const int*)d_in[2];

    static int smem_set = 0;
    if (!smem_set) {
        cudaFuncSetAttribute(ksim, cudaFuncAttributeMaxDynamicSharedMemorySize, SM_TOTAL);
        smem_set = 1;
    }

    knorm<<<dim3(NB, 2), 256>>>(text, video);
    ksim<<<dim3(32, NB), 256, SM_TOTAL>>>(mask, (float*)d_out);
}

// round 14
// speedup vs baseline: 1.4293x; 1.0842x over previous
#include <cuda_runtime.h>
#include <cuda_bf16.h>
#include <math.h>
#include <stdint.h>

// Shapes
#define NB   64
#define T1   33
#define TL   32
#define I1   197
#define IP   224      // padded i
#define CD   512
#define TEMP 0.07f
#define QS   127.0f
#define OSCALE (TEMP / (QS * QS))
#define NCH  4        // K chunks of 128 (int8: 128B rows)
#define A_CH 8192     // A chunk image: 64 rows x 128B
#define B_CH 28672    // B chunk image: 224 rows x 128B
#define NCTA 2048     // 32 x 64

// Scratch: pre-swizzled, chunk-major int8 SMEM images
__device__ __align__(256) int8_t g_Asw[32 * NCH * A_CH];
__device__ __align__(256) int8_t g_Bsw[NB * NCH * B_CH];
__device__ float g_tti[NB * NB];
__device__ int   g_cnt;

// ---------------------------------------------------------------------------
__device__ __forceinline__ uint32_t smem_u32(const void* p) {
    uint32_t a;
    asm("{ .reg .u64 t; cvta.to.shared.u64 t, %1; cvt.u32.u64 %0, t; }"
        : "=r"(a) : "l"(p));
    return a;
}
#define SWZ(o) ((o) ^ ((((uint32_t)(o)) >> 3) & 0x70u))

__device__ __forceinline__ void bulk_ld(uint32_t dst, const void* src,
                                        uint32_t bytes, uint32_t mbar) {
    asm volatile(
        "cp.async.bulk.shared::cluster.global.mbarrier::complete_tx::bytes "
        "[%0], [%1], %2, [%3];"
        :: "r"(dst), "l"(src), "r"(bytes), "r"(mbar) : "memory");
}
__device__ __forceinline__ void mbar_init(uint32_t m, uint32_t cnt) {
    asm volatile("mbarrier.init.shared.b64 [%0], %1;" :: "r"(m), "r"(cnt) : "memory");
}
__device__ __forceinline__ void mbar_expect(uint32_t m, uint32_t bytes) {
    asm volatile("mbarrier.arrive.expect_tx.shared.b64 _, [%0], %1;"
                 :: "r"(m), "r"(bytes) : "memory");
}
__device__ __forceinline__ void mbar_arrive(uint32_t m) {
    asm volatile("mbarrier.arrive.shared.b64 _, [%0];" :: "r"(m) : "memory");
}
#define MBAR_WAIT(addr, par) do {                                               \
    uint32_t _m = (addr), _p = (par), _d;                                       \
    asm volatile("{\n\t.reg .pred p;\n\t"                                       \
        "mbarrier.try_wait.parity.acquire.cta.shared::cta.b64 p, [%1], %2;\n\t" \
        "selp.b32 %0, 1, 0, p;\n\t}" : "=r"(_d) : "r"(_m), "r"(_p) : "memory"); \
    if (!_d) {                                                                  \
        asm volatile("{\n\t.reg .pred P1;\n\tWL_%=:\n\t"                        \
            "mbarrier.try_wait.parity.acquire.cta.shared::cta.b64 P1, [%0], %1, 0x989680;\n\t" \
            "@P1 bra.uni WD_%=;\n\tbra.uni WL_%=;\n\tWD_%=:\n\t}"               \
            :: "r"(_m), "r"(_p) : "memory");                                    \
    }                                                                           \
} while (0)

__device__ __forceinline__ void ldm_x4(uint32_t* r, uint32_t a) {
    asm volatile("ldmatrix.sync.aligned.m8n8.x4.shared.b16 {%0,%1,%2,%3}, [%4];"
                 : "=r"(r[0]), "=r"(r[1]), "=r"(r[2]), "=r"(r[3]) : "r"(a));
}
__device__ __forceinline__ void ldm_x2(uint32_t* r, uint32_t a) {
    asm volatile("ldmatrix.sync.aligned.m8n8.x2.shared.b16 {%0,%1}, [%2];"
                 : "=r"(r[0]), "=r"(r[1]) : "r"(a));
}
__device__ __forceinline__ void mma_s8(int* d, const uint32_t* a,
                                       uint32_t b0, uint32_t b1) {
    asm volatile(
        "mma.sync.aligned.m16n8k32.row.col.s32.s8.s8.s32 "
        "{%0,%1,%2,%3}, {%4,%5,%6,%7}, {%8,%9}, {%0,%1,%2,%3};"
        : "+r"(d[0]), "+r"(d[1]), "+r"(d[2]), "+r"(d[3])
        : "r"(a[0]), "r"(a[1]), "r"(a[2]), "r"(a[3]), "r"(b0), "r"(b1));
}

__device__ __forceinline__ int8_t to_s8(float v) {
    return (int8_t)__float2int_rn(v * QS);
}

// ---------------------------------------------------------------------------
// knorm: grid (64,5), block 256.
//   by==0  : text norm, 2 cols/thread (float2), 33 rows.
//   by=1..4: video norm d-slice of 128 cols; 2 threads/col split the t-range
//            (98/99 rows each), totals combined through smem. 256 video CTAs.
// int8 output written directly in swizzled chunk-major (K=128) SMEM image.
// ---------------------------------------------------------------------------
__global__ void knorm(const float* __restrict__ text, const float* __restrict__ video) {
    const int b = blockIdx.x, tid = threadIdx.x, by = blockIdx.y;
    if (by == 0) {
        if (b == 0 && tid == 0) g_cnt = 0;
        const int d = 2 * tid;
        const float2* p2 = (const float2*)(text + (size_t)b * T1 * CD) + tid;
        float s0 = 0.f, s1 = 0.f;
#pragma unroll
        for (int t = 0; t < T1; t++) {
            float2 v = p2[t * (CD / 2)];
            s0 += v.x * v.x; s1 += v.y * v.y;
        }
        float i0 = 1.0f / sqrtf(s0), i1 = 1.0f / sqrtf(s1);
        int8_t* base = g_Asw + (((size_t)(b >> 1)) * NCH + (d >> 7)) * A_CH;
        uint32_t colb = d & 127;
#pragma unroll 4
        for (int t = 0; t < TL; t++) {
            float2 v = p2[(t + 1) * (CD / 2)];
            int row = (b & 1) * 32 + t;
            uchar2 o = { (unsigned char)to_s8(v.x * i0), (unsigned char)to_s8(v.y * i1) };
            *(uchar2*)(base + SWZ(row * 128 + colb)) = o;
        }
    } else {
        __shared__ float sh[256];
        const int c    = tid & 127;            // column within slice
        const int half = tid >> 7;             // t-range half
        const int col  = (by - 1) * 128 + c;   // global d column
        const float* p = video + (size_t)b * I1 * CD + col;
        const int t0 = half ? 98 : 0;
        const int t1 = half ? I1 : 98;
        float s = 0.f;
#pragma unroll 16
        for (int t = t0; t < t1; t++) { float v = p[t * CD]; s += v * v; }
        sh[tid] = s;
        __syncthreads();
        float inv = 1.0f / sqrtf(sh[c] + sh[128 + c]);
        int8_t* base = g_Bsw + ((size_t)b * NCH + (by - 1)) * B_CH;  // col>>7 == by-1
#pragma unroll 8
        for (int t = t0; t < t1; t++)
            base[SWZ(t * 128 + c)] = to_s8(p[t * CD] * inv);
        if (half) {
#pragma unroll
            for (int t = I1; t < IP; t++)
                base[SWZ(t * 128 + c)] = 0;
        }
    }
}

// ---------------------------------------------------------------------------
// ksim: CTA (qh,y): D[64,224] = A(64x512)*B(224x512)^T in s8->s32.
// 8 warps 2(M)x4(N), warp tile 32x56, K-chunks of 128 (4 x k32 steps),
// 3-stage bulk ring, occupancy 2. Fused max/mean epilogue + last-CTA loss.
// (Converged config: 59.4 us measured; rotation/double-buffer variants neutral.)
// ---------------------------------------------------------------------------
#define SM_RMAX  0
#define SM_MBF   1024
#define SM_MBE   1088
#define SM_STG   2048
#define STG_SZ   (A_CH + B_CH)              // 36864
#define SM_TOTAL (SM_STG + 3 * STG_SZ)      // 112640

__global__ void __launch_bounds__(256, 2)
ksim(const int* __restrict__ amask, float* __restrict__ out) {
    extern __shared__ char smem[];
    __shared__ int lastflag;
    const uint32_t sb = smem_u32(smem);
    const int tid = threadIdx.x, wid = tid >> 5, lid = tid & 31;
    const int wm = wid & 1, wn = wid >> 1;
    const int qh = blockIdx.x, y = blockIdx.y;

    const int8_t* Asrc = g_Asw + (size_t)qh * NCH * A_CH;
    const int8_t* Bsrc = g_Bsw + (size_t)y * NCH * B_CH;

    if (tid == 0) {
#pragma unroll
        for (int s = 0; s < 3; s++) {
            mbar_init(sb + SM_MBF + 8 * s, 1);
            mbar_init(sb + SM_MBE + 8 * s, 8);
        }
    }
    __syncthreads();
    if (tid == 0) {
#pragma unroll
        for (int s = 0; s < 3; s++) {                 // prologue: chunks 0..2
            uint32_t mb = sb + SM_MBF + 8 * s;
            uint32_t st = sb + SM_STG + s * STG_SZ;
            mbar_expect(mb, STG_SZ);
            bulk_ld(st,        Asrc + (size_t)s * A_CH, A_CH, mb);
            bulk_ld(st + A_CH, Bsrc + (size_t)s * B_CH, B_CH, mb);
        }
    }

    int acc[2][7][4];
#pragma unroll
    for (int mi = 0; mi < 2; mi++)
#pragma unroll
        for (int nj = 0; nj < 7; nj++)
#pragma unroll
            for (int d = 0; d < 4; d++) acc[mi][nj][d] = 0;

    // Precomputed swizzled fragment offsets; per-ks offset folds as XOR of kb
    // (bits 5-6 of the base byte offsets are zero within a 32B-aligned k-seg).
    const int arow = 32 * wm + (lid & 15);
    const int brow = 56 * wn + (lid & 15);
    const int btr  = 56 * wn + 48 + (lid & 7);
    const uint32_t chi = ((uint32_t)lid >> 4) * 16;
    const uint32_t cht = (((uint32_t)lid >> 3) & 1) * 16;
    const uint32_t swA0 = SWZ((uint32_t)(arow)      * 128 + chi);
    const uint32_t swA1 = SWZ((uint32_t)(arow + 16) * 128 + chi);
    const uint32_t swB0 = SWZ((uint32_t)(brow)      * 128 + chi);
    const uint32_t swB1 = SWZ((uint32_t)(brow + 16) * 128 + chi);
    const uint32_t swB2 = SWZ((uint32_t)(brow + 32) * 128 + chi);
    const uint32_t swBT = SWZ((uint32_t)(btr)       * 128 + cht);

    int cs = 0;
    uint32_t ph = 0, eph = 0;

#pragma unroll 1
    for (int c = 0; c < NCH; c++) {
        const int s = cs;
        cs = (cs == 2) ? 0 : cs + 1;
        MBAR_WAIT(sb + SM_MBF + 8 * s, (ph >> s) & 1);
        ph ^= (1u << s);
        const uint32_t stA = sb + SM_STG + s * STG_SZ;
        const uint32_t stB = stA + A_CH;

#pragma unroll
        for (int ks = 0; ks < 4; ks++) {
            const uint32_t kb = (uint32_t)ks * 32;
            uint32_t af[2][4], bf[3][4], bt[2];
            ldm_x4(af[0], stA + (swA0 ^ kb));
            ldm_x4(af[1], stA + (swA1 ^ kb));
            ldm_x4(bf[0], stB + (swB0 ^ kb));
            ldm_x4(bf[1], stB + (swB1 ^ kb));
            ldm_x4(bf[2], stB + (swB2 ^ kb));
            ldm_x2(bt,    stB + (swBT ^ kb));
#pragma unroll
            for (int mi = 0; mi < 2; mi++) {
#pragma unroll
                for (int ni = 0; ni < 3; ni++) {
                    mma_s8(acc[mi][2 * ni],     af[mi], bf[ni][0], bf[ni][2]);
                    mma_s8(acc[mi][2 * ni + 1], af[mi], bf[ni][1], bf[ni][3]);
                }
                mma_s8(acc[mi][6], af[mi], bt[0], bt[1]);
            }
        }
        if (lid == 0) mbar_arrive(sb + SM_MBE + 8 * s);

        if (tid == 0 && c < NCH - 3) {                // refill stage s, chunk c+3
            MBAR_WAIT(sb + SM_MBE + 8 * s, (eph >> s) & 1);
            eph ^= (1u << s);
            uint32_t mb = sb + SM_MBF + 8 * s;
            mbar_expect(mb, STG_SZ);
            bulk_ld(stA, Asrc + (size_t)(c + 3) * A_CH, A_CH, mb);
            bulk_ld(stB, Bsrc + (size_t)(c + 3) * B_CH, B_CH, mb);
        }
    }

    // ---- Epilogue: per-row int max over i (mask i>=197) -> masked mean over t
    float* rowmax = (float*)(smem + SM_RMAX);          // [64][4]
#pragma unroll
    for (int mi = 0; mi < 2; mi++)
#pragma unroll
        for (int h = 0; h < 2; h++) {
            int m = -2147483647;
#pragma unroll
            for (int nj = 0; nj < 7; nj++)
#pragma unroll
                for (int e = 0; e < 2; e++) {
                    int col = 56 * wn + 8 * nj + 2 * (lid & 3) + e;
                    int v = acc[mi][nj][2 * h + e];
                    if (col < I1) m = max(m, v);
                }
            m = max(m, __shfl_xor_sync(0xffffffffu, m, 1));
            m = max(m, __shfl_xor_sync(0xffffffffu, m, 2));
            if ((lid & 3) == 0) {
                int row = 32 * wm + 16 * mi + 8 * h + (lid >> 2);
                rowmax[4 * row + wn] = (float)m;
            }
        }
    __syncthreads();

    if (tid < 64) {
        int row = tid;
        float m = fmaxf(fmaxf(rowmax[4 * row], rowmax[4 * row + 1]),
                        fmaxf(rowmax[4 * row + 2], rowmax[4 * row + 3]));
        int xl = row >> 5, t = row & 31;
        int x = 2 * qh + xl;
        int mk = amask[x * T1 + 1 + t] != 0;
        float v = mk ? m * OSCALE : 0.f;
        float cnt = mk ? 1.f : 0.f;
#pragma unroll
        for (int o = 16; o > 0; o >>= 1) {
            v   += __shfl_xor_sync(0xffffffffu, v, o);
            cnt += __shfl_xor_sync(0xffffffffu, cnt, o);
        }
        if (t == 0) g_tti[x * NB + y] = v / fmaxf(cnt, 1e-6f);
    }
    __syncthreads();

    // ---- Last CTA computes the loss
    if (tid == 0) {
        __threadfence();
        lastflag = (atomicAdd(&g_cnt, 1) == NCTA - 1);
    }
    __syncthreads();
    if (lastflag) {
        __threadfence();
        float* sl = (float*)(smem + SM_RMAX);
#pragma unroll 1
        for (int rep = 0; rep < 8; rep++) {
            int x = 8 * wid + rep;
            const float* row = g_tti + x * NB;
            float e = expf(row[lid]) + expf(row[lid + 32]);
#pragma unroll
            for (int o = 16; o > 0; o >>= 1) e += __shfl_xor_sync(0xffffffffu, e, o);
            if (lid == 0) sl[x] = -logf(expf(row[x]) / e + 1e-20f);
        }
        __syncthreads();
        if (tid < 32) {
            float s = sl[lid] + sl[lid + 32];
#pragma unroll
            for (int o = 16; o > 0; o >>= 1) s += __shfl_xor_sync(0xffffffffu, s, o);
            if (lid == 0) out[0] = s * (1.0f / NB);
        }
    }
}

// ---------------------------------------------------------------------------
extern "C" void kernel_launch(void* const* d_in, const int* in_sizes, int n_in,
                              void* d_out, int out_size) {
    const float* text  = (const float*)d_in[0];
    const float* video = (const float*)d_in[1];
    const int*   mask  = (const int*)d_in[2];

    static int smem_set = 0;
    if (!smem_set) {
        cudaFuncSetAttribute(ksim, cudaFuncAttributeMaxDynamicSharedMemorySize, SM_TOTAL);
        smem_set = 1;
    }

    knorm<<<dim3(NB, 5), 256>>>(text, video);
    ksim<<<dim3(32, NB), 256, SM_TOTAL>>>(mask, (float*)d_out);
}